// round 17
// baseline (speedup 1.0000x reference)
#include <cuda_runtime.h>
#include <cstddef>
#include <cstdint>

// ---------------- compile-time Gaussian weights (win=11, sigma=1.5) ----------
__host__ __device__ __forceinline__ constexpr float gw(int t) {
    return (t == 0  || t == 10) ? 0.00102848f
         : (t == 1  || t == 9 ) ? 0.00759876f
         : (t == 2  || t == 8 ) ? 0.03600078f
         : (t == 3  || t == 7 ) ? 0.10936057f
         : (t == 4  || t == 6 ) ? 0.21300557f
         :                        0.26601165f;   // t == 5
}

// ---------------- packed f32x2 helpers (sm_100+) ----------------
__device__ __forceinline__ uint64_t bcast2(float w) {
    uint64_t r; asm("mov.b64 %0, {%1, %1};" : "=l"(r) : "f"(w)); return r;
}
__device__ __forceinline__ uint64_t pk2(float x, float y) {
    uint64_t r; asm("mov.b64 %0, {%1, %2};" : "=l"(r) : "f"(x), "f"(y)); return r;
}
__device__ __forceinline__ float2 unpk(uint64_t v) {
    float2 p; asm("mov.b64 {%0, %1}, %2;" : "=f"(p.x), "=f"(p.y) : "l"(v)); return p;
}
__device__ __forceinline__ void fma2(uint64_t& d, uint64_t a, uint64_t b) {
    asm("fma.rn.f32x2 %0, %1, %2, %0;" : "+l"(d) : "l"(a), "l"(b));
}
__device__ __forceinline__ uint64_t mul2(uint64_t a, uint64_t b) {
    uint64_t d; asm("mul.rn.f32x2 %0, %1, %2;" : "=l"(d) : "l"(a), "l"(b)); return d;
}

#define TILE_W 32
#define TILE_H 64
#define IN_W   42          // TILE_W + 10
#define IN_H   74          // data rows (TILE_H + 10)
#define IN_HP  76          // hs rows incl. 2 pad rows (group-10 reads to row 75)
#define NTHREADS 384       // 12 warps; 2 blocks/SM -> 24 warps/SM

#define IMG_W 512
#define IMG_H 512
#define OUT_W 502
#define OUT_H 502
#define NCH   3

#define HS4_STRIDE 132     // 4 fields interleaved (float4 per col), 16B rows, CF
#define HS1_STRIDE 33      // xy-blur scalar plane, odd stride (scalar access only!)

#define S1_TASKS (IN_H * 4)   // 296 <= 384: single non-divergent round
#define S2_ROWS  6
#define S2_GROUPS 11          // groups 0..10 -> rows 0..65 (>= TILE_H=64)

static constexpr float C1v = 6.5025f;    // (0.01*255)^2
static constexpr float C2v = 58.5225f;   // (0.03*255)^2

// double-buffered hs: 2 x 76 x (132+33) floats = 25080 -> 100320 B -> 2 blk/SM
#define BUF_FLOATS (IN_HP * (HS4_STRIDE + HS1_STRIDE))
#define SMEM_FLOATS (2 * BUF_FLOATS)

__global__ void __launch_bounds__(NTHREADS, 2)
ssim_kernel(const float* __restrict__ X, const float* __restrict__ Y,
            float* __restrict__ out)
{
    extern __shared__ float sm[];

    const int tid = threadIdx.x;
    const int c0  = blockIdx.x * TILE_W;
    const int r0  = blockIdx.y * TILE_H;
    const int n   = blockIdx.z;

    const int s2c  = tid & 31;    // stage-2 column
    const int s2rg = tid >> 5;    // stage-2 row group (6 rows each, 11 active)

    // 6 broadcast weight pairs (symmetric kernel), hoisted into registers
    uint64_t ww[6];
#pragma unroll
    for (int t = 0; t < 6; t++) ww[t] = bcast2(gw(t));

    // stage-1 task decomposition (channel-invariant)
    const int s1g  = tid / IN_H;          // 0..3 col-group (for tid<296)
    const int s1r  = tid - s1g * IN_H;    // 0..73 row
    const int s1g8 = s1g * 8;
    int gr = r0 + s1r; if (gr > IMG_H - 1) gr = IMG_H - 1;   // clamp (guarded)
    const size_t rowbase = (size_t)gr * IMG_W;
    // chunk columns, clamped for the last col-tile (corrupt cells are
    // only consumed by outputs that the write guard discards)
    int cc[5];
#pragma unroll
    for (int q = 0; q < 4; q++) {
        int c = c0 + s1g8 + 4 * q; if (c > IMG_W - 4) c = IMG_W - 4;
        cc[q] = c;
    }
    { int c = c0 + s1g8 + 16; if (c > IMG_W - 2) c = IMG_W - 2; cc[4] = c; }

    float sacc[S2_ROWS];
#pragma unroll
    for (int j = 0; j < S2_ROWS; j++) sacc[j] = 0.0f;

    for (int ch = 0; ch < NCH; ++ch) {
        float* buf = sm + (ch & 1) * BUF_FLOATS;
        float* hs4 = buf;
        float* hs1 = buf + IN_HP * HS4_STRIDE;

        // ---- stage 1: horizontal blur of 5 fields, inputs via LDG ----
        if (tid < S1_TASKS) {
            const float* Xr = X + (size_t)(n * NCH + ch) * (IMG_W * IMG_H) + rowbase;
            const float* Yr = Y + (size_t)(n * NCH + ch) * (IMG_W * IMG_H) + rowbase;

            uint64_t a01[8], a23[8];
            float a4[8];
#pragma unroll
            for (int j = 0; j < 8; j++) { a01[j] = 0ull; a23[j] = 0ull; a4[j] = 0.0f; }

            float4 xq, yq; float2 xt, yt;
#pragma unroll
            for (int k = 0; k < 18; k++) {
                if ((k & 3) == 0) {
                    if (k < 16) {
                        xq = *reinterpret_cast<const float4*>(Xr + cc[k >> 2]);
                        yq = *reinterpret_cast<const float4*>(Yr + cc[k >> 2]);
                    } else {
                        xt = *reinterpret_cast<const float2*>(Xr + cc[4]);
                        yt = *reinterpret_cast<const float2*>(Yr + cc[4]);
                    }
                }
                float x, y;
                if (k < 16) {
                    x = ((k & 3) == 0) ? xq.x : ((k & 3) == 1) ? xq.y
                      : ((k & 3) == 2) ? xq.z : xq.w;
                    y = ((k & 3) == 0) ? yq.x : ((k & 3) == 1) ? yq.y
                      : ((k & 3) == 2) ? yq.z : yq.w;
                } else {
                    x = ((k & 1) == 0) ? xt.x : xt.y;
                    y = ((k & 1) == 0) ? yt.x : yt.y;
                }
                uint64_t xyp = pk2(x, y);            // (x, y)
                uint64_t sqp = mul2(xyp, xyp);       // (x^2, y^2)
                float xy = x * y;
#pragma unroll
                for (int j = 0; j < 8; j++) {
                    const int t = k - j;
                    if (t >= 0 && t < 11) {
                        const int tm = (t < 6) ? t : 10 - t;
                        fma2(a01[j], xyp, ww[tm]);   // blur(x), blur(y)
                        fma2(a23[j], sqp, ww[tm]);   // blur(x2), blur(y2)
                        a4[j] = fmaf(xy, gw(t), a4[j]);  // blur(xy), FFMA-imm
                    }
                }
            }
            float* h4 = hs4 + s1r * HS4_STRIDE + 4 * s1g8;
            float* h1 = hs1 + s1r * HS1_STRIDE + s1g8;
#pragma unroll
            for (int j = 0; j < 8; j++) {
                *reinterpret_cast<uint64_t*>(h4 + 4 * j)     = a01[j];
                *reinterpret_cast<uint64_t*>(h4 + 4 * j + 2) = a23[j];
                h1[j] = a4[j];   // scalar: hs1 stride is odd (alignment!)
            }
        }
        __syncthreads();   // hs(ch) complete; prior s2 on this buffer finished
                           // two iterations ago (barrier chain), so no 2nd sync

        // ---- stage 2: vertical blur (f32x2-packed) + SSIM map, 6 rows ----
        if (s2rg < S2_GROUPS) {
            uint64_t b01[S2_ROWS], b23[S2_ROWS];
            float b4[S2_ROWS];
#pragma unroll
            for (int j = 0; j < S2_ROWS; j++) { b01[j] = 0ull; b23[j] = 0ull; b4[j] = 0.0f; }

            const float* h4 = hs4 + (s2rg * S2_ROWS) * HS4_STRIDE + 4 * s2c;
            const float* h1 = hs1 + (s2rg * S2_ROWS) * HS1_STRIDE + s2c;
#pragma unroll
            for (int k = 0; k < S2_ROWS + 10; k++) {   // 16 rows (max row 75 < 76)
                ulonglong2 v = *reinterpret_cast<const ulonglong2*>(h4 + k * HS4_STRIDE);
                float v4 = h1[k * HS1_STRIDE];
#pragma unroll
                for (int j = 0; j < S2_ROWS; j++) {
                    const int t = k - j;
                    if (t >= 0 && t < 11) {
                        const int tm = (t < 6) ? t : 10 - t;
                        fma2(b01[j], v.x, ww[tm]);   // mu1, mu2
                        fma2(b23[j], v.y, ww[tm]);   // blur(x2), blur(y2)
                        b4[j] = fmaf(v4, gw(t), b4[j]);
                    }
                }
            }
#pragma unroll
            for (int j = 0; j < S2_ROWS; j++) {
                float2 mu  = unpk(b01[j]);               // mu1, mu2
                uint64_t msqp = mul2(b01[j], b01[j]);    // mu1^2, mu2^2
                float2 msq = unpk(msqp);
                float2 sg  = unpk(b23[j]);               // blur(x2), blur(y2)
                float m12 = mu.x * mu.y;
                float s1  = sg.x - msq.x;
                float s2v = sg.y - msq.y;
                float s12 = b4[j] - m12;
                float num = (2.0f * s12 + C2v) * (2.0f * m12 + C1v);
                float den = (s1 + s2v + C2v) * (msq.x + msq.y + C1v);
                sacc[j] += __fdividef(num, den);
            }
        }
        // no barrier here: next iteration's stage-1 writes the OTHER buffer
    }

    // ---- write: 1 - mean over channels ----
    if (s2rg < S2_GROUPS) {
#pragma unroll
        for (int j = 0; j < S2_ROWS; j++) {
            int tr = s2rg * S2_ROWS + j;
            int oh = r0 + tr;
            int ow = c0 + s2c;
            if (tr < TILE_H && oh < OUT_H && ow < OUT_W) {
                out[((size_t)n * OUT_H + oh) * OUT_W + ow] =
                    1.0f - sacc[j] * (1.0f / 3.0f);
            }
        }
    }
}

extern "C" void kernel_launch(void* const* d_in, const int* in_sizes, int n_in,
                              void* d_out, int out_size)
{
    const float* X = (const float*)d_in[0];
    const float* Y = (const float*)d_in[1];
    float* out = (float*)d_out;

    const int smem_bytes = SMEM_FLOATS * (int)sizeof(float);  // 100320
    cudaFuncSetAttribute(ssim_kernel,
                         cudaFuncAttributeMaxDynamicSharedMemorySize,
                         smem_bytes);

    dim3 grid((OUT_W + TILE_W - 1) / TILE_W,   // 16
              (OUT_H + TILE_H - 1) / TILE_H,   // 8
              16);                             // batch -> 2048 blocks
    ssim_kernel<<<grid, NTHREADS, smem_bytes>>>(X, Y, out);
}